// round 1
// baseline (speedup 1.0000x reference)
#include <cuda_runtime.h>

#define NN     200000
#define NEDGE  6400000
#define TDIM   6
#define MDIM   10
#define RROUNDS 3
#define GIN    14
#define GOUT   4

// Scratch (static device globals — no allocation allowed).
// Row strides padded for aligned vector ld/red:
//   round-0 feature space: stride 8 floats (32B rows)
//   fingerprint space:     stride 16 floats (64B rows)
__device__ __align__(256) float g_xs [NN * 8];   // read-only gather source (x_member padded)
__device__ __align__(256) float g_x6 [NN * 8];   // round-0 accumulator (x_member + nbr sum)
__device__ __align__(256) float g_r  [NN * 16];  // current r (gather source)
__device__ __align__(256) float g_acc[NN * 16];  // r + neighbor-sum accumulator
__device__ float g_f[MDIM];                      // fingerprint accumulator

// ---------------------------------------------------------------------------
// init: pad/copy x_member into gather source + accumulator, zero g_f
// ---------------------------------------------------------------------------
__global__ void k_init(const float* __restrict__ xm) {
    int n = blockIdx.x * blockDim.x + threadIdx.x;
    if (n < MDIM) g_f[n] = 0.f;
    if (n >= NN) return;
    float v0 = xm[n * 6 + 0], v1 = xm[n * 6 + 1], v2 = xm[n * 6 + 2];
    float v3 = xm[n * 6 + 3], v4 = xm[n * 6 + 4], v5 = xm[n * 6 + 5];
    float4 a = make_float4(v0, v1, v2, v3);
    float4 b = make_float4(v4, v5, 0.f, 0.f);
    *reinterpret_cast<float4*>(g_xs + (size_t)n * 8)     = a;
    *reinterpret_cast<float4*>(g_xs + (size_t)n * 8 + 4) = b;
    *reinterpret_cast<float4*>(g_x6 + (size_t)n * 8)     = a;
    *reinterpret_cast<float4*>(g_x6 + (size_t)n * 8 + 4) = b;
}

// ---------------------------------------------------------------------------
// Vector reductions (no return value -> REDG, cheaper than ATOMG)
// ---------------------------------------------------------------------------
__device__ __forceinline__ void red_add_v4(float* p, float4 v) {
    asm volatile("red.global.add.v4.f32 [%0], {%1,%2,%3,%4};"
                 :: "l"(p), "f"(v.x), "f"(v.y), "f"(v.z), "f"(v.w) : "memory");
}
__device__ __forceinline__ void red_add_v2(float* p, float2 v) {
    asm volatile("red.global.add.v2.f32 [%0], {%1,%2};"
                 :: "l"(p), "f"(v.x), "f"(v.y) : "memory");
}

// ---------------------------------------------------------------------------
// edge kernels: gather row of src, scatter-add into row of dst
// ---------------------------------------------------------------------------
__global__ void k_edge0(const int* __restrict__ src, const int* __restrict__ dst) {
    int e = blockIdx.x * blockDim.x + threadIdx.x;
    if (e >= NEDGE) return;
    int s = __ldg(src + e);
    int d = __ldg(dst + e);
    const float* rp = g_xs + (size_t)s * 8;
    float4 a = *reinterpret_cast<const float4*>(rp);
    float2 c = *reinterpret_cast<const float2*>(rp + 4);
    float* op = g_x6 + (size_t)d * 8;
    red_add_v4(op, a);
    red_add_v2(op + 4, c);
}

__global__ void k_edgeR(const int* __restrict__ src, const int* __restrict__ dst) {
    int e = blockIdx.x * blockDim.x + threadIdx.x;
    if (e >= NEDGE) return;
    int s = __ldg(src + e);
    int d = __ldg(dst + e);
    const float* rp = g_r + (size_t)s * 16;
    float4 a = *reinterpret_cast<const float4*>(rp);
    float4 b = *reinterpret_cast<const float4*>(rp + 4);
    float2 c = *reinterpret_cast<const float2*>(rp + 8);
    float* op = g_acc + (size_t)d * 16;
    red_add_v4(op, a);
    red_add_v4(op + 4, b);
    red_add_v2(op + 8, c);
}

// ---------------------------------------------------------------------------
// fingerprint accumulation: warp shfl reduce -> shared -> global
// ---------------------------------------------------------------------------
__device__ __forceinline__ void accum_f(float p[MDIM], float* sf, int t) {
#pragma unroll
    for (int m = 0; m < MDIM; m++) {
#pragma unroll
        for (int off = 16; off; off >>= 1)
            p[m] += __shfl_down_sync(0xffffffffu, p[m], off);
    }
    if ((t & 31) == 0) {
#pragma unroll
        for (int m = 0; m < MDIM; m++) atomicAdd(&sf[m], p[m]);
    }
    __syncthreads();
    if (t < MDIM) atomicAdd(&g_f[t], sf[t]);
}

// ---------------------------------------------------------------------------
// node kernel, round 0: r = sigmoid((x + nbr) @ H0); f += softmax(r*w0)
// writes r into both g_r (gather src) and g_acc (accumulator for round 1)
// ---------------------------------------------------------------------------
__global__ void k_node0(const float* __restrict__ H0, const float* __restrict__ Wsc) {
    __shared__ float sH[TDIM * MDIM];
    __shared__ float sf[MDIM];
    int t = threadIdx.x;
    if (t < TDIM * MDIM) sH[t] = H0[t];
    if (t < MDIM) sf[t] = 0.f;
    __syncthreads();

    int n = blockIdx.x * blockDim.x + t;
    float p[MDIM];
    if (n < NN) {
        const float* ap = g_x6 + (size_t)n * 8;
        float in0[TDIM];
#pragma unroll
        for (int j = 0; j < TDIM; j++) in0[j] = ap[j];
        float w = __ldg(Wsc);
#pragma unroll
        for (int m = 0; m < MDIM; m++) {
            float z = 0.f;
#pragma unroll
            for (int j = 0; j < TDIM; j++) z = fmaf(in0[j], sH[j * MDIM + m], z);
            p[m] = 1.f / (1.f + __expf(-z));
        }
        float* rp = g_r   + (size_t)n * 16;
        float* cp = g_acc + (size_t)n * 16;
#pragma unroll
        for (int m = 0; m < MDIM; m++) { rp[m] = p[m]; cp[m] = p[m]; }
        // softmax(p * w)
        float mx = -1e30f;
#pragma unroll
        for (int m = 0; m < MDIM; m++) mx = fmaxf(mx, p[m] * w);
        float ssum = 0.f;
#pragma unroll
        for (int m = 0; m < MDIM; m++) { p[m] = __expf(p[m] * w - mx); ssum += p[m]; }
        float inv = 1.f / ssum;
#pragma unroll
        for (int m = 0; m < MDIM; m++) p[m] *= inv;
    } else {
#pragma unroll
        for (int m = 0; m < MDIM; m++) p[m] = 0.f;
    }
    accum_f(p, sf, t);
}

// ---------------------------------------------------------------------------
// node kernel, rounds 1..R: r = sigmoid((r + nbr) @ H); f += softmax(r*w)
// ---------------------------------------------------------------------------
__global__ void k_nodeR(const float* __restrict__ H, const float* __restrict__ Wsc,
                        int write_acc) {
    __shared__ float sH[MDIM * MDIM];
    __shared__ float sf[MDIM];
    int t = threadIdx.x;
    if (t < MDIM * MDIM) sH[t] = H[t];
    if (t < MDIM) sf[t] = 0.f;
    __syncthreads();

    int n = blockIdx.x * blockDim.x + t;
    float p[MDIM];
    if (n < NN) {
        const float* ap = g_acc + (size_t)n * 16;
        float in0[MDIM];
#pragma unroll
        for (int j = 0; j < MDIM; j++) in0[j] = ap[j];
        float w = __ldg(Wsc);
#pragma unroll
        for (int m = 0; m < MDIM; m++) {
            float z = 0.f;
#pragma unroll
            for (int j = 0; j < MDIM; j++) z = fmaf(in0[j], sH[j * MDIM + m], z);
            p[m] = 1.f / (1.f + __expf(-z));
        }
        float* rp = g_r + (size_t)n * 16;
#pragma unroll
        for (int m = 0; m < MDIM; m++) rp[m] = p[m];
        if (write_acc) {
            float* cp = g_acc + (size_t)n * 16;
#pragma unroll
            for (int m = 0; m < MDIM; m++) cp[m] = p[m];
        }
        float mx = -1e30f;
#pragma unroll
        for (int m = 0; m < MDIM; m++) mx = fmaxf(mx, p[m] * w);
        float ssum = 0.f;
#pragma unroll
        for (int m = 0; m < MDIM; m++) { p[m] = __expf(p[m] * w - mx); ssum += p[m]; }
        float inv = 1.f / ssum;
#pragma unroll
        for (int m = 0; m < MDIM; m++) p[m] *= inv;
    } else {
#pragma unroll
        for (int m = 0; m < MDIM; m++) p[m] = 0.f;
    }
    accum_f(p, sf, t);
}

// ---------------------------------------------------------------------------
// final: group perceptron + merge  -> out[3]
// ---------------------------------------------------------------------------
__global__ void k_final(const float* __restrict__ xg, const float* __restrict__ Wg,
                        const float* __restrict__ Wm, float* __restrict__ out) {
    if (threadIdx.x != 0) return;
    float go[GOUT];
#pragma unroll
    for (int j = 0; j < GOUT; j++) {
        float acc = 0.f;
#pragma unroll
        for (int i = 0; i < GIN; i++) acc = fmaf(xg[i], Wg[i * GOUT + j], acc);
        go[j] = acc;
    }
#pragma unroll
    for (int o = 0; o < 3; o++) {
        float acc = 0.f;
#pragma unroll
        for (int k = 0; k < MDIM; k++) acc = fmaf(g_f[k], Wm[k * 3 + o], acc);
#pragma unroll
        for (int j = 0; j < GOUT; j++) acc = fmaf(go[j], Wm[(MDIM + j) * 3 + o], acc);
        out[o] = acc;
    }
}

extern "C" void kernel_launch(void* const* d_in, const int* in_sizes, int n_in,
                              void* d_out, int out_size) {
    const float* xm   = (const float*)d_in[0];
    const float* xg   = (const float*)d_in[1];
    const int*   esrc = (const int*)  d_in[2];
    const int*   edst = (const int*)  d_in[3];
    const float* H0   = (const float*)d_in[4];
    const float* Hs   = (const float*)d_in[5];
    const float* Wsc  = (const float*)d_in[6];
    const float* Wg   = (const float*)d_in[7];
    const float* Wm   = (const float*)d_in[8];
    float* out = (float*)d_out;

    const int BT = 256;
    int nb_n = (NN + BT - 1) / BT;
    int nb_e = (NEDGE + BT - 1) / BT;

    k_init <<<nb_n, BT>>>(xm);
    k_edge0<<<nb_e, BT>>>(esrc, edst);
    k_node0<<<nb_n, BT>>>(H0, Wsc);
    for (int L = 1; L <= RROUNDS; L++) {
        k_edgeR<<<nb_e, BT>>>(esrc, edst);
        k_nodeR<<<nb_n, BT>>>(Hs + (size_t)(L - 1) * MDIM * MDIM, Wsc + L,
                              (L == RROUNDS) ? 0 : 1);
    }
    k_final<<<1, 32>>>(xg, Wg, Wm, out);
}

// round 2
// speedup vs baseline: 1.4878x; 1.4878x over previous
#include <cuda_runtime.h>
#include <cuda_fp16.h>

#define NN      200000
#define NEDGE   6400000
#define TDIM    6
#define MDIM    10
#define RROUNDS 3
#define GIN     14
#define GOUT    4
#define SCAN_B  256
#define NBLK    782          // ceil(NN / 256)

// ---- static device scratch (no allocation allowed) ----
__device__ __align__(256) __half g_hx[NN * 8];    // x_member fp16, stride 8 halves (16B)
__device__ __align__(256) __half g_hA[NN * 16];   // r buffer A, stride 16 halves (32B)
__device__ __align__(256) __half g_hB[NN * 16];   // r buffer B
__device__ int   g_cnt[NN];
__device__ int   g_off[NN + 1];
__device__ int   g_cur[NN];
__device__ int   g_bsum[1024];
__device__ int   g_csr[NEDGE];
__device__ float g_f[MDIM];

// ---- half2 pack/unpack helpers ----
__device__ __forceinline__ float2 h2f(unsigned u) {
    __half2 h = *reinterpret_cast<const __half2*>(&u);
    return __half22float2(h);
}
__device__ __forceinline__ unsigned f2h(float a, float b) {
    __half2 h = __floats2half2_rn(a, b);
    return *reinterpret_cast<unsigned*>(&h);
}

// ---------------------------------------------------------------------------
// init: zero counters + g_f, convert x_member rows to fp16 (padded to 8)
// ---------------------------------------------------------------------------
__global__ void k_init(const float* __restrict__ xm) {
    int n = blockIdx.x * blockDim.x + threadIdx.x;
    if (n < MDIM) g_f[n] = 0.f;
    if (n >= NN) return;
    g_cnt[n] = 0;
    const float* p = xm + (size_t)n * 6;
    uint4 o;
    o.x = f2h(p[0], p[1]);
    o.y = f2h(p[2], p[3]);
    o.z = f2h(p[4], p[5]);
    o.w = 0u;
    *reinterpret_cast<uint4*>(g_hx + (size_t)n * 8) = o;
}

// ---------------------------------------------------------------------------
// CSR build: histogram -> 2-level exclusive scan -> bucket scatter
// ---------------------------------------------------------------------------
__global__ void k_hist(const int* __restrict__ dst) {
    int e = blockIdx.x * blockDim.x + threadIdx.x;
    if (e >= NEDGE) return;
    atomicAdd(&g_cnt[__ldg(dst + e)], 1);   // result unused -> RED
}

__global__ void k_scan1() {
    __shared__ int s[SCAN_B];
    int t = threadIdx.x;
    int n = blockIdx.x * SCAN_B + t;
    int v = (n < NN) ? g_cnt[n] : 0;
    s[t] = v;
    __syncthreads();
#pragma unroll
    for (int o = 1; o < SCAN_B; o <<= 1) {
        int x = (t >= o) ? s[t - o] : 0;
        __syncthreads();
        s[t] += x;
        __syncthreads();
    }
    if (n < NN) g_off[n] = s[t] - v;               // exclusive within block
    if (t == SCAN_B - 1) g_bsum[blockIdx.x] = s[t]; // block total
}

__global__ void k_scan2() {   // 1 block, 1024 threads, NBLK <= 1024
    __shared__ int s[1024];
    int t = threadIdx.x;
    int v = (t < NBLK) ? g_bsum[t] : 0;
    s[t] = v;
    __syncthreads();
#pragma unroll
    for (int o = 1; o < 1024; o <<= 1) {
        int x = (t >= o) ? s[t - o] : 0;
        __syncthreads();
        s[t] += x;
        __syncthreads();
    }
    if (t < NBLK) g_bsum[t] = s[t] - v;            // exclusive block offsets
}

__global__ void k_scan3() {
    int n = blockIdx.x * blockDim.x + threadIdx.x;
    if (n >= NN) return;
    int o = g_off[n] + g_bsum[n >> 8];
    g_off[n] = o;
    g_cur[n] = o;
    if (n == 0) g_off[NN] = NEDGE;
}

__global__ void k_scatter(const int* __restrict__ src, const int* __restrict__ dst) {
    int e = blockIdx.x * blockDim.x + threadIdx.x;
    if (e >= NEDGE) return;
    int d = __ldg(dst + e);
    int pos = atomicAdd(&g_cur[d], 1);
    g_csr[pos] = __ldg(src + e);
}

// ---------------------------------------------------------------------------
// fingerprint accumulation: warp shfl reduce -> shared -> global
// ---------------------------------------------------------------------------
__device__ __forceinline__ void accum_f(float p[MDIM], float* sf, int t) {
#pragma unroll
    for (int m = 0; m < MDIM; m++) {
#pragma unroll
        for (int off = 16; off; off >>= 1)
            p[m] += __shfl_down_sync(0xffffffffu, p[m], off);
    }
    if ((t & 31) == 0) {
#pragma unroll
        for (int m = 0; m < MDIM; m++) atomicAdd(&sf[m], p[m]);
    }
    __syncthreads();
    if (t < MDIM) atomicAdd(&g_f[t], sf[t]);
}

// ---- gather-accumulate helpers ----
__device__ __forceinline__ void acc6(float* a, int s) {
    uint4 v = __ldg(reinterpret_cast<const uint4*>(g_hx + (size_t)s * 8));
    float2 f;
    f = h2f(v.x); a[0] += f.x; a[1] += f.y;
    f = h2f(v.y); a[2] += f.x; a[3] += f.y;
    f = h2f(v.z); a[4] += f.x; a[5] += f.y;
}
__device__ __forceinline__ void acc10(float* a, const __half* base, int s) {
    const __half* rp = base + (size_t)s * 16;
    uint4 v = __ldg(reinterpret_cast<const uint4*>(rp));
    unsigned w = __ldg(reinterpret_cast<const unsigned*>(rp + 8));
    float2 f;
    f = h2f(v.x); a[0] += f.x; a[1] += f.y;
    f = h2f(v.y); a[2] += f.x; a[3] += f.y;
    f = h2f(v.z); a[4] += f.x; a[5] += f.y;
    f = h2f(v.w); a[6] += f.x; a[7] += f.y;
    f = h2f(w);   a[8] += f.x; a[9] += f.y;
}

__device__ __forceinline__ void write_row10(__half* base, int n, const float* p) {
    uint4 o;
    o.x = f2h(p[0], p[1]);
    o.y = f2h(p[2], p[3]);
    o.z = f2h(p[4], p[5]);
    o.w = f2h(p[6], p[7]);
    __half* rp = base + (size_t)n * 16;
    *reinterpret_cast<uint4*>(rp)        = o;
    *reinterpret_cast<unsigned*>(rp + 8) = f2h(p[8], p[9]);
}

// ---------------------------------------------------------------------------
// round 0 (fused edge+node): r = sigmoid((x + nbr)@H0); f += softmax(r*w)
// reads g_hx (CSR gather), writes g_hA
// ---------------------------------------------------------------------------
__global__ void k_round0(const float* __restrict__ H0, const float* __restrict__ Wsc) {
    __shared__ float sH[TDIM * MDIM];
    __shared__ float sf[MDIM];
    int t = threadIdx.x;
    if (t < TDIM * MDIM) sH[t] = H0[t];
    if (t < MDIM) sf[t] = 0.f;
    __syncthreads();

    int n = blockIdx.x * blockDim.x + t;
    float p[MDIM];
    if (n < NN) {
        float a[TDIM] = {0, 0, 0, 0, 0, 0};
        acc6(a, n);                                // self term
        int e = g_off[n], end = g_off[n + 1];
        for (; e + 4 <= end; e += 4) {
            int s0 = g_csr[e], s1 = g_csr[e + 1], s2 = g_csr[e + 2], s3 = g_csr[e + 3];
            acc6(a, s0); acc6(a, s1); acc6(a, s2); acc6(a, s3);
        }
        for (; e < end; e++) acc6(a, g_csr[e]);

        float w = __ldg(Wsc);
#pragma unroll
        for (int m = 0; m < MDIM; m++) {
            float z = 0.f;
#pragma unroll
            for (int j = 0; j < TDIM; j++) z = fmaf(a[j], sH[j * MDIM + m], z);
            p[m] = 1.f / (1.f + __expf(-z));
        }
        write_row10(g_hA, n, p);
        float mx = -1e30f;
#pragma unroll
        for (int m = 0; m < MDIM; m++) mx = fmaxf(mx, p[m] * w);
        float ssum = 0.f;
#pragma unroll
        for (int m = 0; m < MDIM; m++) { p[m] = __expf(p[m] * w - mx); ssum += p[m]; }
        float inv = 1.f / ssum;
#pragma unroll
        for (int m = 0; m < MDIM; m++) p[m] *= inv;
    } else {
#pragma unroll
        for (int m = 0; m < MDIM; m++) p[m] = 0.f;
    }
    accum_f(p, sf, t);
}

// ---------------------------------------------------------------------------
// rounds 1..R (fused): r' = sigmoid((r + nbr)@H); f += softmax(r'*w)
// flip=0: read g_hA write g_hB;  flip=1: read g_hB write g_hA
// ---------------------------------------------------------------------------
__global__ void k_roundR(const float* __restrict__ H, const float* __restrict__ Wsc,
                         int flip) {
    __shared__ float sH[MDIM * MDIM];
    __shared__ float sf[MDIM];
    int t = threadIdx.x;
    if (t < MDIM * MDIM) sH[t] = H[t];
    if (t < MDIM) sf[t] = 0.f;
    __syncthreads();

    const __half* src = flip ? g_hB : g_hA;
    __half*       dst = flip ? g_hA : g_hB;

    int n = blockIdx.x * blockDim.x + t;
    float p[MDIM];
    if (n < NN) {
        float a[MDIM] = {0, 0, 0, 0, 0, 0, 0, 0, 0, 0};
        acc10(a, src, n);                          // self term
        int e = g_off[n], end = g_off[n + 1];
        for (; e + 4 <= end; e += 4) {
            int s0 = g_csr[e], s1 = g_csr[e + 1], s2 = g_csr[e + 2], s3 = g_csr[e + 3];
            acc10(a, src, s0); acc10(a, src, s1); acc10(a, src, s2); acc10(a, src, s3);
        }
        for (; e < end; e++) acc10(a, src, g_csr[e]);

        float w = __ldg(Wsc);
#pragma unroll
        for (int m = 0; m < MDIM; m++) {
            float z = 0.f;
#pragma unroll
            for (int j = 0; j < MDIM; j++) z = fmaf(a[j], sH[j * MDIM + m], z);
            p[m] = 1.f / (1.f + __expf(-z));
        }
        write_row10(dst, n, p);
        float mx = -1e30f;
#pragma unroll
        for (int m = 0; m < MDIM; m++) mx = fmaxf(mx, p[m] * w);
        float ssum = 0.f;
#pragma unroll
        for (int m = 0; m < MDIM; m++) { p[m] = __expf(p[m] * w - mx); ssum += p[m]; }
        float inv = 1.f / ssum;
#pragma unroll
        for (int m = 0; m < MDIM; m++) p[m] *= inv;
    } else {
#pragma unroll
        for (int m = 0; m < MDIM; m++) p[m] = 0.f;
    }
    accum_f(p, sf, t);
}

// ---------------------------------------------------------------------------
// final: group perceptron + merge -> out[3]
// ---------------------------------------------------------------------------
__global__ void k_final(const float* __restrict__ xg, const float* __restrict__ Wg,
                        const float* __restrict__ Wm, float* __restrict__ out) {
    if (threadIdx.x != 0) return;
    float go[GOUT];
#pragma unroll
    for (int j = 0; j < GOUT; j++) {
        float acc = 0.f;
#pragma unroll
        for (int i = 0; i < GIN; i++) acc = fmaf(xg[i], Wg[i * GOUT + j], acc);
        go[j] = acc;
    }
#pragma unroll
    for (int o = 0; o < 3; o++) {
        float acc = 0.f;
#pragma unroll
        for (int k = 0; k < MDIM; k++) acc = fmaf(g_f[k], Wm[k * 3 + o], acc);
#pragma unroll
        for (int j = 0; j < GOUT; j++) acc = fmaf(go[j], Wm[(MDIM + j) * 3 + o], acc);
        out[o] = acc;
    }
}

extern "C" void kernel_launch(void* const* d_in, const int* in_sizes, int n_in,
                              void* d_out, int out_size) {
    const float* xm   = (const float*)d_in[0];
    const float* xg   = (const float*)d_in[1];
    const int*   esrc = (const int*)  d_in[2];
    const int*   edst = (const int*)  d_in[3];
    const float* H0   = (const float*)d_in[4];
    const float* Hs   = (const float*)d_in[5];
    const float* Wsc  = (const float*)d_in[6];
    const float* Wg   = (const float*)d_in[7];
    const float* Wm   = (const float*)d_in[8];
    float* out = (float*)d_out;

    const int BT = 256;
    int nb_n = (NN + BT - 1) / BT;       // 782
    int nb_e = (NEDGE + BT - 1) / BT;

    k_init   <<<nb_n, BT>>>(xm);
    k_hist   <<<nb_e, BT>>>(edst);
    k_scan1  <<<NBLK, SCAN_B>>>();
    k_scan2  <<<1, 1024>>>();
    k_scan3  <<<nb_n, BT>>>();
    k_scatter<<<nb_e, BT>>>(esrc, edst);

    k_round0 <<<nb_n, BT>>>(H0, Wsc);
    k_roundR <<<nb_n, BT>>>(Hs,                     Wsc + 1, 0); // A -> B
    k_roundR <<<nb_n, BT>>>(Hs + MDIM * MDIM,       Wsc + 2, 1); // B -> A
    k_roundR <<<nb_n, BT>>>(Hs + 2 * MDIM * MDIM,   Wsc + 3, 0); // A -> B
    k_final  <<<1, 32>>>(xg, Wg, Wm, out);
}